// round 1
// baseline (speedup 1.0000x reference)
#include <cuda_runtime.h>

#define B_N 64
#define A_N 10647
#define G_N 50
#define C_N 9
#define NCHUNK 6
#define CH 1775          // 6*1775 = 10650 >= 10647
#define NTHR 128
#define NA 14            // ceil(1775/128)

__device__ unsigned long long g_keys[B_N * NCHUNK * G_N];
__device__ float g_bce[B_N * NCHUNK];
__device__ float g_perimg[B_N];

__device__ __forceinline__ float clog(float x) { return fmaxf(__logf(x), -100.0f); }

// Kernel 1: per (batch, anchor-chunk): per-gt best-IoU anchor (packed key) + partial bce0 sum.
__global__ __launch_bounds__(NTHR) void yolo_k1(const float* __restrict__ pred,
                                                const float* __restrict__ bboxes,
                                                const int* __restrict__ classes) {
    const int b = blockIdx.y, c = blockIdx.x;
    const int tid = threadIdx.x, lane = tid & 31, warp = tid >> 5;

    __shared__ float sg[5][G_N];                 // gx1, gy1, gx2, gy2, area_g
    __shared__ int sval[G_N];
    __shared__ unsigned long long swk[G_N][NTHR / 32];
    __shared__ float sbce[NTHR / 32];

    if (tid < G_N) {
        const float* gb = bboxes + (b * G_N + tid) * 4;
        float x1 = gb[0], y1 = gb[1], x2 = gb[2], y2 = gb[3];
        float cx = (x1 + x2) * 0.5f, cy = (y1 + y2) * 0.5f;
        float w = x2 - x1, h = y2 - y1;
        float gx1 = cx - w * 0.5f, gy1 = cy - h * 0.5f;
        float gx2 = cx + w * 0.5f, gy2 = cy + h * 0.5f;
        sg[0][tid] = gx1; sg[1][tid] = gy1; sg[2][tid] = gx2; sg[3][tid] = gy2;
        sg[4][tid] = (gx2 - gx1) * (gy2 - gy1);   // replicate ref arithmetic exactly
        sval[tid] = (classes[b * G_N + tid] != -1);
    }
    __syncthreads();

    const int base = c * CH;
    const int end  = min(base + CH, A_N);

    // Anchor data register-resident (avoid smem crossbar bound).
    float px1[NA], py1[NA], px2[NA], py2[NA], pap[NA];
    int aid[NA];
    float bce = 0.0f;

#pragma unroll
    for (int i = 0; i < NA; i++) {
        int a = base + tid + i * NTHR;
        bool ok = a < end;
        int al = ok ? a : (end - 1);
        const float* row = pred + (long long)(b * A_N + al) * 14;   // 8B-aligned (56B rows)
        float2 p01 = *(const float2*)(row);
        float2 p23 = *(const float2*)(row + 2);
        float conf = row[4];
        float cx = p01.x, cy = p01.y, w = p23.x, h = p23.y;
        float x1 = cx - w * 0.5f, x2 = cx + w * 0.5f;
        float y1 = cy - h * 0.5f, y2 = cy + h * 0.5f;
        float ap = (x2 - x1) * (y2 - y1);
        if (!ok) { x1 = 3.0e38f; x2 = 3.0e38f; y1 = 3.0e38f; y2 = 3.0e38f; ap = 0.0f; }
        px1[i] = x1; px2[i] = x2; py1[i] = y1; py2[i] = y2; pap[i] = ap;
        aid[i] = ok ? a : 0x7FFFFFFF;
        if (ok) bce += -clog(1.0f - conf);
    }

    // Per-gt IoU argmax. Invalid gts (class == -1) are masked in the ref; skip them.
    for (int g = 0; g < G_N; g++) {
        if (!sval[g]) continue;
        float gx1 = sg[0][g], gy1 = sg[1][g], gx2 = sg[2][g], gy2 = sg[3][g];
        float age = sg[4][g] + 1e-16f;
        float biou = -1.0f;
        int bidx = 0x7FFFFFFF;
#pragma unroll
        for (int i = 0; i < NA; i++) {
            float iw = fmaxf(fminf(px2[i], gx2) - fmaxf(px1[i], gx1), 0.0f);
            float ih = fmaxf(fminf(py2[i], gy2) - fmaxf(py1[i], gy1), 0.0f);
            float inter = iw * ih;
            float den = (pap[i] + age) - inter;
            float iou = __fdividef(inter, den);
            // strict > keeps first (smallest) index within this thread's ascending scan
            if (iou > biou) { biou = iou; bidx = aid[i]; }
        }
        // Pack: high = iou bits (iou >= 0, bit compare == float compare),
        // low = ~index so max-reduce tie-breaks toward the smallest anchor index.
        unsigned long long pk = ((unsigned long long)__float_as_uint(biou) << 32)
                              | (unsigned)(0xFFFFFFFFu - (unsigned)bidx);
#pragma unroll
        for (int s = 16; s; s >>= 1) {
            unsigned long long o = __shfl_xor_sync(0xFFFFFFFFu, pk, s);
            pk = (o > pk) ? o : pk;
        }
        if (lane == 0) swk[g][warp] = pk;
    }

    // Deterministic bce0 partial-sum reduction (fixed tree order).
#pragma unroll
    for (int s = 16; s; s >>= 1) bce += __shfl_xor_sync(0xFFFFFFFFu, bce, s);
    if (lane == 0) sbce[warp] = bce;
    __syncthreads();
    if (tid == 0) g_bce[b * NCHUNK + c] = (sbce[0] + sbce[1]) + (sbce[2] + sbce[3]);

    if (tid < G_N) {
        unsigned long long k = 0ULL;
        if (sval[tid]) {
            unsigned long long a0 = swk[tid][0], a1 = swk[tid][1];
            unsigned long long a2 = swk[tid][2], a3 = swk[tid][3];
            unsigned long long m0 = a0 > a1 ? a0 : a1;
            unsigned long long m1 = a2 > a3 ? a2 : a3;
            k = m0 > m1 ? m0 : m1;
        }
        g_keys[(b * NCHUNK + c) * G_N + tid] = k;
    }
}

// Kernel 2: per batch: combine chunk keys, gather best anchor row, per-gt loss -> per_img.
__global__ void yolo_k2(const float* __restrict__ pred,
                        const float* __restrict__ bboxes,
                        const int* __restrict__ classes) {
    const int b = blockIdx.x, tid = threadIdx.x;
    __shared__ float sper[G_N];
    __shared__ int sval[G_N];
    __shared__ float stot;

    if (tid == 0) {
        float t = 0.0f;
        for (int j = 0; j < NCHUNK; j++) t += g_bce[b * NCHUNK + j];
        stot = t;
    }
    __syncthreads();
    float tot0 = stot;

    if (tid < G_N) {
        int cls = classes[b * G_N + tid];
        sval[tid] = (cls != -1);
        float pg = 0.0f;
        if (cls != -1) {
            unsigned long long k = 0ULL;
            for (int j = 0; j < NCHUNK; j++) {
                unsigned long long v = g_keys[(b * NCHUNK + j) * G_N + tid];
                k = v > k ? v : k;
            }
            unsigned aidx = 0xFFFFFFFFu - (unsigned)(k & 0xFFFFFFFFULL);
            const float* row = pred + (long long)(b * A_N + aidx) * 14;
            const float* gb = bboxes + (b * G_N + tid) * 4;
            float x1 = gb[0], y1 = gb[1], x2 = gb[2], y2 = gb[3];
            float gcx = (x1 + x2) * 0.5f, gcy = (y1 + y2) * 0.5f;
            float gw = x2 - x1, gh = y2 - y1;
            float d0 = row[0] - gcx, d1 = row[1] - gcy;
            float d2 = row[2] - gw,  d3 = row[3] - gh;
            float coord = 5.0f * ((d0 * d0 + d1 * d1) + (d2 * d2 + d3 * d3));
            float conf = row[4];
            float conf_obj = -clog(conf);
            float clsl = 0.0f;
#pragma unroll
            for (int cc = 0; cc < C_N; cc++) {
                float p = row[5 + cc];
                clsl += (cc == cls) ? -clog(p) : -clog(1.0f - p);
            }
            float bce0b = -clog(1.0f - conf);
            float noobj = 0.5f * (tot0 - bce0b);
            pg = (coord + conf_obj) + (clsl + noobj);
        }
        sper[tid] = pg;
    }
    __syncthreads();

    if (tid == 0) {
        float s = 0.0f;
        int has = 0;
        for (int g = 0; g < G_N; g++) { s += sper[g]; has |= sval[g]; }
        g_perimg[b] = has ? s : 0.5f * tot0;
    }
}

// Kernel 3: deterministic final sum.
__global__ void yolo_k3(float* out) {
    if (threadIdx.x == 0) {
        float s = 0.0f;
        for (int b = 0; b < B_N; b++) s += g_perimg[b];
        out[0] = s / (float)B_N;
    }
}

extern "C" void kernel_launch(void* const* d_in, const int* in_sizes, int n_in,
                              void* d_out, int out_size) {
    const float* pred    = (const float*)d_in[0];
    const float* bboxes  = (const float*)d_in[1];
    const int*   classes = (const int*)d_in[2];
    float* out = (float*)d_out;

    dim3 g1(NCHUNK, B_N);
    yolo_k1<<<g1, NTHR>>>(pred, bboxes, classes);
    yolo_k2<<<B_N, 64>>>(pred, bboxes, classes);
    yolo_k3<<<1, 32>>>(out);
}

// round 2
// speedup vs baseline: 1.1891x; 1.1891x over previous
#include <cuda_runtime.h>

#define B_N 64
#define A_N 10647
#define G_N 50
#define C_N 9
#define NCHUNK 16
#define CH 666           // 16*666 = 10656 >= 10647
#define NTHR 128
#define NA 6             // ceil(666/128) = 6

__device__ unsigned long long g_keys[B_N * NCHUNK * G_N];
__device__ float g_bce[B_N * NCHUNK];
__device__ float g_perimg[B_N];

__device__ __forceinline__ float clog(float x) { return fmaxf(__logf(x), -100.0f); }

// Kernel 1: per (batch, anchor-chunk): per-gt best-IoU anchor (packed key) + partial bce0 sum.
__global__ __launch_bounds__(NTHR, 7) void yolo_k1(const float* __restrict__ pred,
                                                   const float* __restrict__ bboxes,
                                                   const int* __restrict__ classes) {
    const int b = blockIdx.y, c = blockIdx.x;
    const int tid = threadIdx.x, lane = tid & 31, warp = tid >> 5;

    __shared__ float sg[5][G_N];                 // gx1, gy1, gx2, gy2, area_g
    __shared__ int sval[G_N];
    __shared__ unsigned long long swk[G_N][NTHR / 32];
    __shared__ float sbce[NTHR / 32];

    if (tid < G_N) {
        const float* gb = bboxes + (b * G_N + tid) * 4;
        float x1 = gb[0], y1 = gb[1], x2 = gb[2], y2 = gb[3];
        float cx = (x1 + x2) * 0.5f, cy = (y1 + y2) * 0.5f;
        float w = x2 - x1, h = y2 - y1;
        float gx1 = cx - w * 0.5f, gy1 = cy - h * 0.5f;
        float gx2 = cx + w * 0.5f, gy2 = cy + h * 0.5f;
        sg[0][tid] = gx1; sg[1][tid] = gy1; sg[2][tid] = gx2; sg[3][tid] = gy2;
        sg[4][tid] = (gx2 - gx1) * (gy2 - gy1);   // replicate ref arithmetic exactly
        sval[tid] = (classes[b * G_N + tid] != -1);
    }
    __syncthreads();

    const int base = c * CH;
    const int end  = min(base + CH, A_N);

    // Anchor data register-resident (avoid smem crossbar bound).
    float px1[NA], py1[NA], px2[NA], py2[NA], pap[NA];
    int aid[NA];
    float bce = 0.0f;

#pragma unroll
    for (int i = 0; i < NA; i++) {
        int a = base + tid + i * NTHR;
        bool ok = a < end;
        int al = ok ? a : (end - 1);
        const float* row = pred + (long long)(b * A_N + al) * 14;   // 8B-aligned (56B rows)
        float2 p01 = *(const float2*)(row);
        float2 p23 = *(const float2*)(row + 2);
        float conf = row[4];
        float cx = p01.x, cy = p01.y, w = p23.x, h = p23.y;
        float x1 = cx - w * 0.5f, x2 = cx + w * 0.5f;
        float y1 = cy - h * 0.5f, y2 = cy + h * 0.5f;
        float ap = (x2 - x1) * (y2 - y1);
        if (!ok) { x1 = 3.0e38f; x2 = 3.0e38f; y1 = 3.0e38f; y2 = 3.0e38f; ap = 0.0f; }
        px1[i] = x1; px2[i] = x2; py1[i] = y1; py2[i] = y2; pap[i] = ap;
        aid[i] = ok ? a : 0x7FFFFFFF;
        if (ok) bce += -clog(1.0f - conf);
    }

    // Per-gt IoU argmax via cross-multiplication (no per-pair divide).
    // Invalid gts (class == -1) are masked in the ref; skip them (uniform branch).
    for (int g = 0; g < G_N; g++) {
        if (!sval[g]) continue;
        float gx1 = sg[0][g], gy1 = sg[1][g], gx2 = sg[2][g], gy2 = sg[3][g];
        float age = sg[4][g] + 1e-16f;
        float binter = -1.0f, bden = 1.0f;       // first (always-valid) slot overwrites
        int bidx = 0;
#pragma unroll
        for (int i = 0; i < NA; i++) {
            float iw = fmaxf(fminf(px2[i], gx2) - fmaxf(px1[i], gx1), 0.0f);
            float ih = fmaxf(fminf(py2[i], gy2) - fmaxf(py1[i], gy1), 0.0f);
            float inter = iw * ih;
            float den = (pap[i] + age) - inter;  // > 0 always (areas positive)
            // inter/den > binter/bden  <=>  inter*bden > binter*den  (dens > 0)
            bool better = inter * bden > binter * den;
            binter = better ? inter : binter;
            bden   = better ? den   : bden;
            bidx   = better ? aid[i] : bidx;
        }
        float biou = __fdividef(binter, bden);   // one divide per (thread, gt)
        // Pack: high = iou bits (iou >= 0, bit compare == float compare),
        // low = ~index so max-reduce tie-breaks toward the smallest anchor index.
        unsigned long long pk = ((unsigned long long)__float_as_uint(biou) << 32)
                              | (unsigned)(0xFFFFFFFFu - (unsigned)bidx);
#pragma unroll
        for (int s = 16; s; s >>= 1) {
            unsigned long long o = __shfl_xor_sync(0xFFFFFFFFu, pk, s);
            pk = (o > pk) ? o : pk;
        }
        if (lane == 0) swk[g][warp] = pk;
    }

    // Deterministic bce0 partial-sum reduction (fixed tree order).
#pragma unroll
    for (int s = 16; s; s >>= 1) bce += __shfl_xor_sync(0xFFFFFFFFu, bce, s);
    if (lane == 0) sbce[warp] = bce;
    __syncthreads();
    if (tid == 0) g_bce[b * NCHUNK + c] = (sbce[0] + sbce[1]) + (sbce[2] + sbce[3]);

    if (tid < G_N) {
        unsigned long long k = 0ULL;
        if (sval[tid]) {
            unsigned long long a0 = swk[tid][0], a1 = swk[tid][1];
            unsigned long long a2 = swk[tid][2], a3 = swk[tid][3];
            unsigned long long m0 = a0 > a1 ? a0 : a1;
            unsigned long long m1 = a2 > a3 ? a2 : a3;
            k = m0 > m1 ? m0 : m1;
        }
        g_keys[(b * NCHUNK + c) * G_N + tid] = k;
    }
}

// Kernel 2: per batch: combine chunk keys, gather best anchor row, per-gt loss -> per_img.
__global__ void yolo_k2(const float* __restrict__ pred,
                        const float* __restrict__ bboxes,
                        const int* __restrict__ classes) {
    const int b = blockIdx.x, tid = threadIdx.x;
    __shared__ float sper[G_N];
    __shared__ int sval[G_N];
    __shared__ float stot;

    if (tid == 0) {
        float t = 0.0f;
        for (int j = 0; j < NCHUNK; j++) t += g_bce[b * NCHUNK + j];
        stot = t;
    }
    __syncthreads();
    float tot0 = stot;

    if (tid < G_N) {
        int cls = classes[b * G_N + tid];
        sval[tid] = (cls != -1);
        float pg = 0.0f;
        if (cls != -1) {
            unsigned long long k = 0ULL;
            for (int j = 0; j < NCHUNK; j++) {
                unsigned long long v = g_keys[(b * NCHUNK + j) * G_N + tid];
                k = v > k ? v : k;
            }
            unsigned aidx = 0xFFFFFFFFu - (unsigned)(k & 0xFFFFFFFFULL);
            const float* row = pred + (long long)(b * A_N + aidx) * 14;
            const float* gb = bboxes + (b * G_N + tid) * 4;
            float x1 = gb[0], y1 = gb[1], x2 = gb[2], y2 = gb[3];
            float gcx = (x1 + x2) * 0.5f, gcy = (y1 + y2) * 0.5f;
            float gw = x2 - x1, gh = y2 - y1;
            float d0 = row[0] - gcx, d1 = row[1] - gcy;
            float d2 = row[2] - gw,  d3 = row[3] - gh;
            float coord = 5.0f * ((d0 * d0 + d1 * d1) + (d2 * d2 + d3 * d3));
            float conf = row[4];
            float conf_obj = -clog(conf);
            float clsl = 0.0f;
#pragma unroll
            for (int cc = 0; cc < C_N; cc++) {
                float p = row[5 + cc];
                clsl += (cc == cls) ? -clog(p) : -clog(1.0f - p);
            }
            float bce0b = -clog(1.0f - conf);
            float noobj = 0.5f * (tot0 - bce0b);
            pg = (coord + conf_obj) + (clsl + noobj);
        }
        sper[tid] = pg;
    }
    __syncthreads();

    if (tid == 0) {
        float s = 0.0f;
        int has = 0;
        for (int g = 0; g < G_N; g++) { s += sper[g]; has |= sval[g]; }
        g_perimg[b] = has ? s : 0.5f * tot0;
    }
}

// Kernel 3: deterministic final sum.
__global__ void yolo_k3(float* out) {
    if (threadIdx.x == 0) {
        float s = 0.0f;
        for (int b = 0; b < B_N; b++) s += g_perimg[b];
        out[0] = s / (float)B_N;
    }
}

extern "C" void kernel_launch(void* const* d_in, const int* in_sizes, int n_in,
                              void* d_out, int out_size) {
    const float* pred    = (const float*)d_in[0];
    const float* bboxes  = (const float*)d_in[1];
    const int*   classes = (const int*)d_in[2];
    float* out = (float*)d_out;

    dim3 g1(NCHUNK, B_N);
    yolo_k1<<<g1, NTHR>>>(pred, bboxes, classes);
    yolo_k2<<<B_N, 64>>>(pred, bboxes, classes);
    yolo_k3<<<1, 32>>>(out);
}

// round 3
// speedup vs baseline: 1.4532x; 1.2221x over previous
#include <cuda_runtime.h>

#define B_N 64
#define A_N 10647
#define G_N 50
#define C_N 9
#define NCHUNK 18
#define CH 592           // 18*592 = 10656 >= 10647
#define NTHR 128
#define NA 5             // ceil(592/128) = 5

__device__ unsigned long long g_keys[B_N * NCHUNK * G_N];
__device__ float g_bce[B_N * NCHUNK];
__device__ float g_perimg[B_N];
__device__ int g_count;

__device__ __forceinline__ float clog(float x) { return fmaxf(__logf(x), -100.0f); }

// Kernel 1: per (batch, anchor-chunk): per-gt best-r anchor (r = inter/S, monotonic in IoU)
// packed key + partial bce0 sum.
__global__ __launch_bounds__(NTHR, 8) void yolo_k1(const float* __restrict__ pred,
                                                   const float* __restrict__ bboxes,
                                                   const int* __restrict__ classes) {
    const int b = blockIdx.y, c = blockIdx.x;
    const int tid = threadIdx.x, lane = tid & 31, warp = tid >> 5;

    if (b == 0 && c == 0 && tid == 0) g_count = 0;   // reset finalize counter per replay

    __shared__ float sg[5][G_N];                 // gx1, gy1, gx2, gy2, area_g
    __shared__ int sval[G_N];
    __shared__ unsigned long long swk[G_N][NTHR / 32];
    __shared__ float sbce[NTHR / 32];

    if (tid < G_N) {
        const float* gb = bboxes + (b * G_N + tid) * 4;
        float x1 = gb[0], y1 = gb[1], x2 = gb[2], y2 = gb[3];
        float cx = (x1 + x2) * 0.5f, cy = (y1 + y2) * 0.5f;
        float w = x2 - x1, h = y2 - y1;
        float gx1 = cx - w * 0.5f, gy1 = cy - h * 0.5f;
        float gx2 = cx + w * 0.5f, gy2 = cy + h * 0.5f;
        sg[0][tid] = gx1; sg[1][tid] = gy1; sg[2][tid] = gx2; sg[3][tid] = gy2;
        sg[4][tid] = (gx2 - gx1) * (gy2 - gy1);   // replicate ref arithmetic exactly
        sval[tid] = (classes[b * G_N + tid] != -1);
    }
    __syncthreads();

    const int base = c * CH;
    const int end  = min(base + CH, A_N);

    // Anchor data register-resident (avoid smem crossbar bound).
    float px1[NA], py1[NA], px2[NA], py2[NA], pap[NA];
    float bce = 0.0f;

#pragma unroll
    for (int i = 0; i < NA; i++) {
        int a = base + tid + i * NTHR;
        bool ok = a < end;
        int al = ok ? a : (end - 1);
        const float* row = pred + (long long)(b * A_N + al) * 14;   // 8B-aligned (56B rows)
        float2 p01 = *(const float2*)(row);
        float2 p23 = *(const float2*)(row + 2);
        float conf = row[4];
        float cx = p01.x, cy = p01.y, w = p23.x, h = p23.y;
        float x1 = cx - w * 0.5f, x2 = cx + w * 0.5f;
        float y1 = cy - h * 0.5f, y2 = cy + h * 0.5f;
        float ap = (x2 - x1) * (y2 - y1);
        if (!ok) { x1 = 3.0e38f; x2 = 3.0e38f; y1 = 3.0e38f; y2 = 3.0e38f; ap = 0.0f; }
        px1[i] = x1; px2[i] = x2; py1[i] = y1; py2[i] = y2; pap[i] = ap;
        if (ok) bce += -clog(1.0f - conf);
    }

    // Per-gt argmax of r = inter / (area_p + area_g + eps).
    // inter2/den2 > inter1/den1  <=>  inter2*S1 > inter1*S2  <=>  r2 > r1  (dens, S > 0),
    // so maximizing r selects the same anchor as maximizing IoU.
    for (int g = 0; g < G_N; g++) {
        if (!sval[g]) continue;
        float gx1 = sg[0][g], gy1 = sg[1][g], gx2 = sg[2][g], gy2 = sg[3][g];
        float age = sg[4][g] + 1e-16f;
        float br = -1.0f;
        int bslot = 0;
#pragma unroll
        for (int i = 0; i < NA; i++) {
            float iw = fmaxf(fminf(px2[i], gx2) - fmaxf(px1[i], gx1), 0.0f);
            float ih = fmaxf(fminf(py2[i], gy2) - fmaxf(py1[i], gy1), 0.0f);
            float inter = iw * ih;
            float S = pap[i] + age;              // > 0 always
            float r = __fdividef(inter, S);      // MUFU.RCP + FMUL (off the alu pipe)
            bool better = r > br;                // strict > keeps smallest slot
            br = fmaxf(br, r);
            bslot = better ? i : bslot;          // SEL with immediate
        }
        int bidx = base + tid + bslot * NTHR;    // slot 0 always valid; pads give r=0
        unsigned rb = __float_as_uint(br);       // br >= 0 -> bit order == float order
        unsigned m = __reduce_max_sync(0xFFFFFFFFu, rb);
        unsigned mask = __ballot_sync(0xFFFFFFFFu, rb == m);
        int src = __ffs(mask) - 1;
        int widx = __shfl_sync(0xFFFFFFFFu, bidx, src);
        if (lane == 0)
            swk[g][warp] = ((unsigned long long)m << 32)
                         | (unsigned)(0xFFFFFFFFu - (unsigned)widx);
    }

    // Deterministic bce0 partial-sum reduction (fixed tree order).
#pragma unroll
    for (int s = 16; s; s >>= 1) bce += __shfl_xor_sync(0xFFFFFFFFu, bce, s);
    if (lane == 0) sbce[warp] = bce;
    __syncthreads();
    if (tid == 0) g_bce[b * NCHUNK + c] = (sbce[0] + sbce[1]) + (sbce[2] + sbce[3]);

    if (tid < G_N) {
        unsigned long long k = 0ULL;
        if (sval[tid]) {
            unsigned long long a0 = swk[tid][0], a1 = swk[tid][1];
            unsigned long long a2 = swk[tid][2], a3 = swk[tid][3];
            unsigned long long m0 = a0 > a1 ? a0 : a1;
            unsigned long long m1 = a2 > a3 ? a2 : a3;
            k = m0 > m1 ? m0 : m1;
        }
        g_keys[(b * NCHUNK + c) * G_N + tid] = k;
    }
}

// Kernel 2: per batch: combine chunk keys, gather best anchor row, per-gt loss -> per_img.
// Last block to finish also does the deterministic final sum (fixed order).
__global__ void yolo_k2(const float* __restrict__ pred,
                        const float* __restrict__ bboxes,
                        const int* __restrict__ classes,
                        float* __restrict__ out) {
    const int b = blockIdx.x, tid = threadIdx.x;
    __shared__ float sper[G_N];
    __shared__ int sval[G_N];
    __shared__ float stot;

    if (tid == 0) {
        float t = 0.0f;
        for (int j = 0; j < NCHUNK; j++) t += g_bce[b * NCHUNK + j];
        stot = t;
    }
    __syncthreads();
    float tot0 = stot;

    if (tid < G_N) {
        int cls = classes[b * G_N + tid];
        sval[tid] = (cls != -1);
        float pg = 0.0f;
        if (cls != -1) {
            unsigned long long k = 0ULL;
            for (int j = 0; j < NCHUNK; j++) {
                unsigned long long v = g_keys[(b * NCHUNK + j) * G_N + tid];
                k = v > k ? v : k;
            }
            unsigned aidx = 0xFFFFFFFFu - (unsigned)(k & 0xFFFFFFFFULL);
            const float* row = pred + (long long)(b * A_N + aidx) * 14;
            const float* gb = bboxes + (b * G_N + tid) * 4;
            float x1 = gb[0], y1 = gb[1], x2 = gb[2], y2 = gb[3];
            float gcx = (x1 + x2) * 0.5f, gcy = (y1 + y2) * 0.5f;
            float gw = x2 - x1, gh = y2 - y1;
            float d0 = row[0] - gcx, d1 = row[1] - gcy;
            float d2 = row[2] - gw,  d3 = row[3] - gh;
            float coord = 5.0f * ((d0 * d0 + d1 * d1) + (d2 * d2 + d3 * d3));
            float conf = row[4];
            float conf_obj = -clog(conf);
            float clsl = 0.0f;
#pragma unroll
            for (int cc = 0; cc < C_N; cc++) {
                float p = row[5 + cc];
                clsl += (cc == cls) ? -clog(p) : -clog(1.0f - p);
            }
            float bce0b = -clog(1.0f - conf);
            float noobj = 0.5f * (tot0 - bce0b);
            pg = (coord + conf_obj) + (clsl + noobj);
        }
        sper[tid] = pg;
    }
    __syncthreads();

    if (tid == 0) {
        float s = 0.0f;
        int has = 0;
        for (int g = 0; g < G_N; g++) { s += sper[g]; has |= sval[g]; }
        g_perimg[b] = has ? s : 0.5f * tot0;
        __threadfence();
        int done = atomicAdd(&g_count, 1);
        if (done == B_N - 1) {
            float t = 0.0f;
            for (int bb = 0; bb < B_N; bb++) t += g_perimg[bb];   // fixed order: deterministic
            out[0] = t / (float)B_N;
            g_count = 0;
        }
    }
}

extern "C" void kernel_launch(void* const* d_in, const int* in_sizes, int n_in,
                              void* d_out, int out_size) {
    const float* pred    = (const float*)d_in[0];
    const float* bboxes  = (const float*)d_in[1];
    const int*   classes = (const int*)d_in[2];
    float* out = (float*)d_out;

    dim3 g1(NCHUNK, B_N);
    yolo_k1<<<g1, NTHR>>>(pred, bboxes, classes);
    yolo_k2<<<B_N, 64>>>(pred, bboxes, classes, out);
}